// round 14
// baseline (speedup 1.0000x reference)
#include <cuda_runtime.h>
#include <cuda_bf16.h>
#include <mma.h>
#include <math.h>

using namespace nvcuda;

#define NMAX 50000
#define EMAX 800000
#define HID  32
#define DIN  128

// ---------------- scratch (static; no cudaMalloc allowed) ----------------
__device__ __align__(128) __nv_bfloat16 g_y1b[NMAX * HID];   // x @ W1_l.T (bf16)
__device__ __align__(128) __nv_bfloat16 g_agg1b[NMAX * HID]; // bf16 edge sums
__device__ __align__(128) float g_r1[NMAX * HID];            // x @ W1_r.T (fp32)
__device__ __align__(128) float g_deg[NMAX];
__device__ __align__(128) float g_z2[NMAX];
__device__ __align__(128) float g_r2[NMAX];
__device__ __align__(128) float g_agg2[NMAX];
__device__ int g_is64;

// ---------------- helpers ----------------
__device__ __forceinline__ unsigned long long fma2(unsigned long long a,
                                                   unsigned long long b,
                                                   unsigned long long c) {
    unsigned long long d;
    asm("fma.rn.f32x2 %0, %1, %2, %3;" : "=l"(d) : "l"(a), "l"(b), "l"(c));
    return d;
}
__device__ __forceinline__ float hsum2(unsigned long long a) {
    float lo, hi;
    asm("mov.b64 {%0, %1}, %2;" : "=f"(lo), "=f"(hi) : "l"(a));
    return lo + hi;
}
// 16-byte reduction of 8 bf16 values
__device__ __forceinline__ void red_add_bf16x8(void* addr, uint4 v) {
#if !defined(__CUDA_ARCH__) || __CUDA_ARCH__ >= 900
    asm volatile("red.global.add.noftz.v4.bf16x2 [%0], {%1, %2, %3, %4};"
                 :: "l"(addr), "r"(v.x), "r"(v.y), "r"(v.z), "r"(v.w)
                 : "memory");
#else
    __nv_bfloat162* p = (__nv_bfloat162*)addr;
    atomicAdd(p + 0, *(__nv_bfloat162*)&v.x);
    atomicAdd(p + 1, *(__nv_bfloat162*)&v.y);
    atomicAdd(p + 2, *(__nv_bfloat162*)&v.z);
    atomicAdd(p + 3, *(__nv_bfloat162*)&v.w);
#endif
}
__device__ __forceinline__ void load_edges4(const void* ei, int E, int e0,
                                            int is64, int* s, int* d) {
    if (is64) {
        longlong4 sv = *(const longlong4*)((const long long*)ei + e0);
        longlong4 dv = *(const longlong4*)((const long long*)ei + E + e0);
        s[0] = (int)sv.x; s[1] = (int)sv.y; s[2] = (int)sv.z; s[3] = (int)sv.w;
        d[0] = (int)dv.x; d[1] = (int)dv.y; d[2] = (int)dv.z; d[3] = (int)dv.w;
    } else {
        int4 sv = *(const int4*)((const int*)ei + e0);
        int4 dv = *(const int4*)((const int*)ei + E + e0);
        s[0] = sv.x; s[1] = sv.y; s[2] = sv.z; s[3] = sv.w;
        d[0] = dv.x; d[1] = dv.y; d[2] = dv.z; d[3] = dv.w;
    }
}

// ================= kernel 1: y1 GEMM via smem-staged tf32 WMMA ================
// 128 threads = 4 warps; block stages a 64-node x tile (32 KB) in smem with a
// coalesced high-MLP load, then warp w computes its 16-node slice of
// y1 = x@W1_l.T (m16n16k8 tf32, B read in place from Wl col-major view).
__global__ void __launch_bounds__(128) k_pre(const float* __restrict__ x,
                                             const float* __restrict__ Wl,
                                             const unsigned int* __restrict__ ei32,
                                             int n) {
    // dtype detect (block 0): ids < 2^31 => int64 storage has odd words == 0
    if (blockIdx.x == 0) {
        __shared__ int found;
        if (threadIdx.x == 0) found = 0;
        __syncthreads();
        for (int i = 1 + 2 * threadIdx.x; i < 4096; i += 2 * blockDim.x)
            if (ei32[i] != 0u) found = 1;  // benign race
        __syncthreads();
        if (threadIdx.x == 0) g_is64 = (found == 0) ? 1 : 0;
    }
    // zero scratch
    {
        int gtid = blockIdx.x * blockDim.x + threadIdx.x;
        int stride = gridDim.x * blockDim.x;
        unsigned int* a32 = (unsigned int*)g_agg1b;
        int tot = n * HID / 2;
        for (int i = gtid; i < tot; i += stride) a32[i] = 0u;
        for (int i = gtid; i < n; i += stride) {
            g_deg[i] = 0.0f;
            g_agg2[i] = 0.0f;
        }
    }

    __shared__ __align__(16) float sx[64 * DIN];       // 32 KB

    int t = threadIdx.x;
    int warp = t >> 5;
    int lane = t & 31;
    int ntile16 = (n + 15) >> 4;
    int nsuper = (ntile16 + 3) >> 2;
    const float4* x4 = (const float4*)x;

    for (int st = blockIdx.x; st < nsuper; st += gridDim.x) {
        int base = st * 64;
#pragma unroll
        for (int i = 0; i < 16; i++) {
            int idx = t + i * 128;
            int node = base + (idx >> 5), k4 = idx & 31;
            float4 v = make_float4(0.f, 0.f, 0.f, 0.f);
            if (node < n) v = x4[node * 32 + k4];
            ((float4*)sx)[idx] = v;
        }
        __syncthreads();

        int tile = st * 4 + warp;
        wmma::fragment<wmma::accumulator, 16, 16, 8, float> accl0, accl1;
        if (tile < ntile16) {
            wmma::fragment<wmma::matrix_a, 16, 16, 8, wmma::precision::tf32,
                           wmma::row_major> fa;
            wmma::fragment<wmma::matrix_b, 16, 16, 8, wmma::precision::tf32,
                           wmma::col_major> fb;
            wmma::fill_fragment(accl0, 0.0f);
            wmma::fill_fragment(accl1, 0.0f);

#pragma unroll
            for (int k0 = 0; k0 < DIN; k0 += 8) {
                wmma::load_matrix_sync(fa, sx + warp * 16 * DIN + k0, DIN);
#pragma unroll
                for (int i = 0; i < fa.num_elements; i++)
                    fa.x[i] = wmma::__float_to_tf32(fa.x[i]);

                wmma::load_matrix_sync(fb, Wl + k0, DIN);            // out 0..15
#pragma unroll
                for (int i = 0; i < fb.num_elements; i++)
                    fb.x[i] = wmma::__float_to_tf32(fb.x[i]);
                wmma::mma_sync(accl0, fa, fb, accl0);

                wmma::load_matrix_sync(fb, Wl + 16 * DIN + k0, DIN); // out 16..31
#pragma unroll
                for (int i = 0; i < fb.num_elements; i++)
                    fb.x[i] = wmma::__float_to_tf32(fb.x[i]);
                wmma::mma_sync(accl1, fa, fb, accl1);
            }
        }

        __syncthreads();   // x tile dead; reuse sx as y1 staging
        if (tile < ntile16) {
            float* stg = sx + warp * 512;               // 16 x 32 floats
            wmma::store_matrix_sync(stg, accl0, 32, wmma::mem_row_major);
            wmma::store_matrix_sync(stg + 16, accl1, 32, wmma::mem_row_major);
            __syncwarp();
            int m0 = tile * 16;
            __nv_bfloat162* y2 = (__nv_bfloat162*)g_y1b;
#pragma unroll
            for (int idx = lane; idx < 256; idx += 32) {
                int row = idx >> 4, cp = idx & 15;
                float f0 = stg[row * 32 + cp * 2];
                float f1 = stg[row * 32 + cp * 2 + 1];
                y2[(m0 + row) * 16 + cp] = __floats2bfloat162_rn(f0, f1);
            }
        }
        __syncthreads();
    }
}

// ================= kernel 2 (fat): r1 GEMM blocks + layer-1 edge scatter ======
#define NB 8
#define GB 444
__global__ void __launch_bounds__(256) k_fat(const float* __restrict__ x,
                                             const float* __restrict__ Wr,
                                             const void* __restrict__ ei,
                                             int n, int E) {
    if (blockIdx.x < GB) {
        // ---------------- r1 GEMM role (fp32-exact scalar) ----------------
        __shared__ __align__(16) float sx[NB * DIN];
        __shared__ float sp[3 * NB * 32];

        int t = threadIdx.x;
        int o = t & 31;
        int h = (t >> 5) & 3;
        int sg = t >> 7;

        const float* wrow = Wr + o * DIN + h * 32;
        ulonglong2 wreg[8];
#pragma unroll
        for (int j = 0; j < 8; j++)
            wreg[j] = ((const ulonglong2*)wrow)[j];

        const float4* x4 = (const float4*)x;
        int nbatch = (n + NB - 1) / NB;

        for (int b = blockIdx.x; b < nbatch; b += GB) {
            int nb0 = b * NB;
            {
                int idx = t;
                int nn = idx >> 5, k4 = idx & 31;
                float4 v = make_float4(0.f, 0.f, 0.f, 0.f);
                if (nb0 + nn < n) v = x4[(nb0 + nn) * 32 + k4];
                ((float4*)sx)[idx] = v;
            }
            __syncthreads();

            float sum[NB / 2];
#pragma unroll
            for (int i = 0; i < NB / 2; i++) {
                int nn = sg + 2 * i;
                const ulonglong2* xp = (const ulonglong2*)(sx + nn * DIN + h * 32);
                unsigned long long aA = 0ull, aB = 0ull;
#pragma unroll
                for (int j = 0; j < 8; j++) {
                    ulonglong2 xv = xp[j];
                    aA = fma2(xv.x, wreg[j].x, aA);
                    aB = fma2(xv.y, wreg[j].y, aB);
                }
                sum[i] = hsum2(aA) + hsum2(aB);
            }
            if (h > 0) {
#pragma unroll
                for (int i = 0; i < NB / 2; i++) {
                    int nn = sg + 2 * i;
                    sp[(h - 1) * (NB * 32) + nn * 32 + o] = sum[i];
                }
            }
            __syncthreads();
            if (h == 0) {
#pragma unroll
                for (int i = 0; i < NB / 2; i++) {
                    int nn = sg + 2 * i;
                    int node = nb0 + nn;
                    if (node < n) {
                        float v = sum[i] + sp[nn * 32 + o]
                                + sp[NB * 32 + nn * 32 + o]
                                + sp[2 * NB * 32 + nn * 32 + o];
                        g_r1[node * 32 + o] = v;
                    }
                }
            }
        }
    } else {
        // ---------------- edge-scatter role ----------------
        int is64 = g_is64;
        int ngroups = E >> 2;
        int t = (blockIdx.x - GB) * 256 + threadIdx.x;
        int g = t >> 2, c = t & 3;

        const uint4* y4 = (const uint4*)g_y1b;
        char* aggb = (char*)g_agg1b;

        if (g < ngroups) {
            int e0 = g * 4;
            int s[4], d[4];
            load_edges4(ei, E, e0, is64, s, d);
            uint4 v[4];
#pragma unroll
            for (int i = 0; i < 4; i++)
                v[i] = y4[s[i] * 4 + c];
#pragma unroll
            for (int i = 0; i < 4; i++)
                red_add_bf16x8(aggb + d[i] * 64 + c * 16, v[i]);
            if (c == 0) {
#pragma unroll
                for (int i = 0; i < 4; i++)
                    atomicAdd(&g_deg[d[i]], 1.0f);
            }
        } else if (g == ngroups) {
            for (int e = ngroups * 4; e < E; e++) {
                int s = is64 ? (int)((const long long*)ei)[e] : ((const int*)ei)[e];
                int d = is64 ? (int)((const long long*)ei)[E + e] : ((const int*)ei)[E + e];
                uint4 v = y4[s * 4 + c];
                red_add_bf16x8(aggb + d * 64 + c * 16, v);
                if (c == 0) atomicAdd(&g_deg[d], 1.0f);
            }
        }
    }
}

// ================= kernel 3: node update + scalar layer-2 projections =========
__global__ void __launch_bounds__(256) k_node1(const float* __restrict__ b1,
                                               const float* __restrict__ W2l,
                                               const float* __restrict__ W2r,
                                               int n) {
    int t = blockIdx.x * blockDim.x + threadIdx.x;
    int node = t >> 3, c = t & 7;
    if (node >= n) return;
    float invd = 1.0f / fmaxf(g_deg[node], 1.0f);
    uint2 ab = ((const uint2*)g_agg1b)[node * 8 + c];
    float2 a0 = __bfloat1622float2(*(__nv_bfloat162*)&ab.x);
    float2 a1 = __bfloat1622float2(*(__nv_bfloat162*)&ab.y);
    float4 r = ((const float4*)g_r1)[node * 8 + c];
    float4 bb = ((const float4*)b1)[c];
    float4 h;
    h.x = fmaxf(fmaf(a0.x, invd, bb.x + r.x), 0.0f);
    h.y = fmaxf(fmaf(a0.y, invd, bb.y + r.y), 0.0f);
    h.z = fmaxf(fmaf(a1.x, invd, bb.z + r.z), 0.0f);
    h.w = fmaxf(fmaf(a1.y, invd, bb.w + r.w), 0.0f);
    float4 wl = ((const float4*)W2l)[c];
    float4 wr = ((const float4*)W2r)[c];
    float zl = h.x * wl.x + h.y * wl.y + h.z * wl.z + h.w * wl.w;
    float zr = h.x * wr.x + h.y * wr.y + h.z * wr.z + h.w * wr.w;
#pragma unroll
    for (int o = 1; o <= 4; o <<= 1) {
        zl += __shfl_xor_sync(0xFFFFFFFFu, zl, o);
        zr += __shfl_xor_sync(0xFFFFFFFFu, zr, o);
    }
    if (c == 0) {
        g_z2[node] = zl;
        g_r2[node] = zr;
    }
}

// ================= kernel 4: layer-2 scalar edge scatter ======================
__global__ void __launch_bounds__(256) k_edge2(const void* __restrict__ ei, int E) {
    int is64 = g_is64;
    int ngroups = E >> 2;
    int g = blockIdx.x * blockDim.x + threadIdx.x;
    if (g < ngroups) {
        int e0 = g * 4;
        int s[4], d[4];
        load_edges4(ei, E, e0, is64, s, d);
        float z[4];
#pragma unroll
        for (int i = 0; i < 4; i++) z[i] = g_z2[s[i]];
#pragma unroll
        for (int i = 0; i < 4; i++) atomicAdd(&g_agg2[d[i]], z[i]);
    } else if (g == ngroups) {
        for (int e = ngroups * 4; e < E; e++) {
            int s = is64 ? (int)((const long long*)ei)[e] : ((const int*)ei)[e];
            int d = is64 ? (int)((const long long*)ei)[E + e] : ((const int*)ei)[E + e];
            atomicAdd(&g_agg2[d], g_z2[s]);
        }
    }
}

// ================= kernel 5: final sigmoid ============
__global__ void k_out(float* __restrict__ out, const float* __restrict__ b2, int n) {
    int i = blockIdx.x * blockDim.x + threadIdx.x;
    if (i < n) {
        float inv = 1.0f / fmaxf(g_deg[i], 1.0f);
        float v = fmaf(g_agg2[i], inv, b2[0] + g_r2[i]);
        out[i] = 1.0f / (1.0f + expf(-v));
    }
}

// ---------------- launch ----------------
extern "C" void kernel_launch(void* const* d_in, const int* in_sizes, int n_in,
                              void* d_out, int out_size) {
    const float* x   = (const float*)d_in[0];
    const void*  ei  = d_in[1];
    const float* W1l = (const float*)d_in[2];
    const float* b1  = (const float*)d_in[3];
    const float* W1r = (const float*)d_in[4];
    const float* W2l = (const float*)d_in[5];
    const float* b2  = (const float*)d_in[6];
    const float* W2r = (const float*)d_in[7];
    float* out = (float*)d_out;

    int n = in_sizes[0] / DIN;
    int E = in_sizes[1] / 2;
    if (n > NMAX) n = NMAX;
    if (E > EMAX) E = EMAX;

    int ntile16 = (n + 15) >> 4;
    int nsuper = (ntile16 + 3) >> 2;
    k_pre<<<nsuper, 128>>>(x, W1l, (const unsigned int*)ei, n);
    int edge_blocks = (E + 4 + 255) / 256;
    k_fat<<<GB + edge_blocks, 256>>>(x, W1r, ei, n, E);
    k_node1<<<(n * 8 + 255) / 256, 256>>>(b1, W2l, W2r, n);
    int ng = (E >> 2) + 1;
    k_edge2<<<(ng + 255) / 256, 256>>>(ei, E);
    k_out<<<(n + 255) / 256, 256>>>(out, b2, n);
}

// round 16
// speedup vs baseline: 1.0859x; 1.0859x over previous
#include <cuda_runtime.h>
#include <cuda_bf16.h>
#include <math.h>
#include <cstdint>

#define NMAX 50000
#define EMAX 800000
#define HID  32
#define DIN  128

// ---------------- scratch (static; no cudaMalloc allowed) ----------------
__device__ __align__(128) __nv_bfloat16 g_y1b[NMAX * HID];   // x @ W1_l.T (bf16)
__device__ __align__(128) __nv_bfloat16 g_agg1b[NMAX * HID]; // bf16 edge sums
__device__ __align__(128) float g_r1[NMAX * HID];            // x @ W1_r.T (fp32)
__device__ __align__(128) float g_deg[NMAX];
__device__ __align__(128) float g_z2[NMAX];
__device__ __align__(128) float g_r2[NMAX];
__device__ __align__(128) float g_agg2[NMAX];
__device__ int g_is64;

// ---------------- helpers ----------------
__device__ __forceinline__ unsigned long long fma2(unsigned long long a,
                                                   unsigned long long b,
                                                   unsigned long long c) {
    unsigned long long d;
    asm("fma.rn.f32x2 %0, %1, %2, %3;" : "=l"(d) : "l"(a), "l"(b), "l"(c));
    return d;
}
__device__ __forceinline__ float hsum2(unsigned long long a) {
    float lo, hi;
    asm("mov.b64 {%0, %1}, %2;" : "=f"(lo), "=f"(hi) : "l"(a));
    return lo + hi;
}
// 16-byte reduction of 8 bf16 values
__device__ __forceinline__ void red_add_bf16x8(void* addr, uint4 v) {
#if !defined(__CUDA_ARCH__) || __CUDA_ARCH__ >= 900
    asm volatile("red.global.add.noftz.v4.bf16x2 [%0], {%1, %2, %3, %4};"
                 :: "l"(addr), "r"(v.x), "r"(v.y), "r"(v.z), "r"(v.w)
                 : "memory");
#else
    __nv_bfloat162* p = (__nv_bfloat162*)addr;
    atomicAdd(p + 0, *(__nv_bfloat162*)&v.x);
    atomicAdd(p + 1, *(__nv_bfloat162*)&v.y);
    atomicAdd(p + 2, *(__nv_bfloat162*)&v.z);
    atomicAdd(p + 3, *(__nv_bfloat162*)&v.w);
#endif
}
__device__ __forceinline__ void load_edges4(const void* ei, int E, int e0,
                                            int is64, int* s, int* d) {
    if (is64) {
        longlong4 sv = *(const longlong4*)((const long long*)ei + e0);
        longlong4 dv = *(const longlong4*)((const long long*)ei + E + e0);
        s[0] = (int)sv.x; s[1] = (int)sv.y; s[2] = (int)sv.z; s[3] = (int)sv.w;
        d[0] = (int)dv.x; d[1] = (int)dv.y; d[2] = (int)dv.z; d[3] = (int)dv.w;
    } else {
        int4 sv = *(const int4*)((const int*)ei + e0);
        int4 dv = *(const int4*)((const int*)ei + E + e0);
        s[0] = sv.x; s[1] = sv.y; s[2] = sv.z; s[3] = sv.w;
        d[0] = dv.x; d[1] = dv.y; d[2] = dv.z; d[3] = dv.w;
    }
}
// cp.async helpers (16B, L1-bypass)
__device__ __forceinline__ void cp_async16(unsigned int dst_smem, const void* src) {
    asm volatile("cp.async.cg.shared.global [%0], [%1], 16;"
                 :: "r"(dst_smem), "l"(src));
}
__device__ __forceinline__ void cp_commit() {
    asm volatile("cp.async.commit_group;");
}
__device__ __forceinline__ void cp_wait0() {
    asm volatile("cp.async.wait_group 0;");
}

// ================= kernel 1: y1 GEMM (bf16) + zero + dtype detect =============
// R8 structure + cp.async double-buffered x tiles: batch b+1's loads are in
// flight while batch b computes, hiding the ~600-cycle global latency.
#define NB 8
__global__ void __launch_bounds__(128) k_pre(const float* __restrict__ x,
                                             const float* __restrict__ Wl,
                                             const unsigned int* __restrict__ ei32,
                                             int n) {
    if (blockIdx.x == 0) {
        __shared__ int found;
        if (threadIdx.x == 0) found = 0;
        __syncthreads();
        for (int i = 1 + 2 * threadIdx.x; i < 4096; i += 2 * blockDim.x)
            if (ei32[i] != 0u) found = 1;  // benign race
        __syncthreads();
        if (threadIdx.x == 0) g_is64 = (found == 0) ? 1 : 0;
    }
    {
        int gtid = blockIdx.x * blockDim.x + threadIdx.x;
        int stride = gridDim.x * blockDim.x;
        unsigned int* a32 = (unsigned int*)g_agg1b;
        int tot = n * HID / 2;
        for (int i = gtid; i < tot; i += stride) a32[i] = 0u;
        for (int i = gtid; i < n; i += stride) {
            g_deg[i] = 0.0f;
            g_agg2[i] = 0.0f;
        }
    }

    __shared__ __align__(16) float sx[2][NB * DIN];    // 2 x 4 KB double buffer
    __shared__ float sp[3 * NB * 32];                  // 3 KB (h=1..3 partials)

    int t = threadIdx.x;
    int o = t & 31;
    int h = (t >> 5) & 3;

    const float* wrow = Wl + o * DIN + h * 32;
    ulonglong2 wreg[8];
#pragma unroll
    for (int j = 0; j < 8; j++)
        wreg[j] = ((const ulonglong2*)wrow)[j];

    const float4* x4 = (const float4*)x;
    int nbatch = (n + NB - 1) / NB;
    unsigned int sbase = (unsigned int)__cvta_generic_to_shared(&sx[0][0]);

    // issue one batch's x tile into buffer `buf`
    auto issue = [&](int bb, int buf) {
        int nb0 = bb * NB;
#pragma unroll
        for (int i = 0; i < 2; i++) {
            int idx = t + i * 128;                     // 0..255 float4 slots
            int nn = idx >> 5, k4 = idx & 31;
            int node = nb0 + nn;
            unsigned int dst = sbase + (unsigned int)(buf * (NB * DIN) * 4 + idx * 16);
            if (node < n) {
                cp_async16(dst, x4 + node * 32 + k4);
            } else {
                float4 z = make_float4(0.f, 0.f, 0.f, 0.f);
                *(float4*)((char*)&sx[0][0] + buf * (NB * DIN) * 4 + idx * 16) = z;
            }
        }
        cp_commit();
    };

    int b = blockIdx.x;
    int cur = 0;
    if (b < nbatch) issue(b, 0);
    for (; b < nbatch; b += gridDim.x) {
        cp_wait0();
        __syncthreads();                   // buf[cur] ready; prev outputs done
        int nb = b + gridDim.x;
        if (nb < nbatch) issue(nb, cur ^ 1);

        int nb0 = b * NB;
        float sum[NB];
#pragma unroll
        for (int nn = 0; nn < NB; nn++) {
            const ulonglong2* xp = (const ulonglong2*)(&sx[cur][nn * DIN + h * 32]);
            unsigned long long aA = 0ull, aB = 0ull;
#pragma unroll
            for (int j = 0; j < 8; j++) {
                ulonglong2 xv = xp[j];
                aA = fma2(xv.x, wreg[j].x, aA);
                aB = fma2(xv.y, wreg[j].y, aB);
            }
            sum[nn] = hsum2(aA) + hsum2(aB);
        }
        if (h > 0) {
#pragma unroll
            for (int nn = 0; nn < NB; nn++)
                sp[(h - 1) * (NB * 32) + nn * 32 + o] = sum[nn];
        }
        __syncthreads();
        if (h == 0) {
#pragma unroll
            for (int nn = 0; nn < NB; nn++) {
                int node = nb0 + nn;
                if (node < n) {
                    float v = sum[nn] + sp[nn * 32 + o]
                            + sp[NB * 32 + nn * 32 + o]
                            + sp[2 * NB * 32 + nn * 32 + o];
                    g_y1b[node * 32 + o] = __float2bfloat16(v);
                }
            }
        }
        cur ^= 1;
    }
}

// ================= kernel 2 (fat): r1 GEMM blocks + layer-1 edge scatter ======
#define GB 444
__global__ void __launch_bounds__(256) k_fat(const float* __restrict__ x,
                                             const float* __restrict__ Wr,
                                             const void* __restrict__ ei,
                                             int n, int E) {
    if (blockIdx.x < GB) {
        // ---------------- r1 GEMM role (fp32, cp.async double-buffered) ------
        __shared__ __align__(16) float sx[2][NB * DIN];
        __shared__ float sp[3 * NB * 32];

        int t = threadIdx.x;
        int o = t & 31;
        int h = (t >> 5) & 3;
        int sg = t >> 7;

        const float* wrow = Wr + o * DIN + h * 32;
        ulonglong2 wreg[8];
#pragma unroll
        for (int j = 0; j < 8; j++)
            wreg[j] = ((const ulonglong2*)wrow)[j];

        const float4* x4 = (const float4*)x;
        int nbatch = (n + NB - 1) / NB;
        unsigned int sbase = (unsigned int)__cvta_generic_to_shared(&sx[0][0]);

        auto issue = [&](int bb, int buf) {
            int nb0 = bb * NB;
            int idx = t;                               // 256 float4 slots
            int nn = idx >> 5, k4 = idx & 31;
            int node = nb0 + nn;
            unsigned int dst = sbase + (unsigned int)(buf * (NB * DIN) * 4 + idx * 16);
            if (node < n) {
                cp_async16(dst, x4 + node * 32 + k4);
            } else {
                float4 z = make_float4(0.f, 0.f, 0.f, 0.f);
                *(float4*)((char*)&sx[0][0] + buf * (NB * DIN) * 4 + idx * 16) = z;
            }
            cp_commit();
        };

        int b = blockIdx.x;
        int cur = 0;
        if (b < nbatch) issue(b, 0);
        for (; b < nbatch; b += GB) {
            cp_wait0();
            __syncthreads();
            int nb = b + GB;
            if (nb < nbatch) issue(nb, cur ^ 1);

            int nb0 = b * NB;
            float sum[NB / 2];
#pragma unroll
            for (int i = 0; i < NB / 2; i++) {
                int nn = sg + 2 * i;
                const ulonglong2* xp =
                    (const ulonglong2*)(&sx[cur][nn * DIN + h * 32]);
                unsigned long long aA = 0ull, aB = 0ull;
#pragma unroll
                for (int j = 0; j < 8; j++) {
                    ulonglong2 xv = xp[j];
                    aA = fma2(xv.x, wreg[j].x, aA);
                    aB = fma2(xv.y, wreg[j].y, aB);
                }
                sum[i] = hsum2(aA) + hsum2(aB);
            }
            if (h > 0) {
#pragma unroll
                for (int i = 0; i < NB / 2; i++) {
                    int nn = sg + 2 * i;
                    sp[(h - 1) * (NB * 32) + nn * 32 + o] = sum[i];
                }
            }
            __syncthreads();
            if (h == 0) {
#pragma unroll
                for (int i = 0; i < NB / 2; i++) {
                    int nn = sg + 2 * i;
                    int node = nb0 + nn;
                    if (node < n) {
                        float v = sum[i] + sp[nn * 32 + o]
                                + sp[NB * 32 + nn * 32 + o]
                                + sp[2 * NB * 32 + nn * 32 + o];
                        g_r1[node * 32 + o] = v;
                    }
                }
            }
            cur ^= 1;
        }
    } else {
        // ---------------- edge-scatter role ----------------
        int is64 = g_is64;
        int ngroups = E >> 2;
        int t = (blockIdx.x - GB) * 256 + threadIdx.x;
        int g = t >> 2, c = t & 3;

        const uint4* y4 = (const uint4*)g_y1b;
        char* aggb = (char*)g_agg1b;

        if (g < ngroups) {
            int e0 = g * 4;
            int s[4], d[4];
            load_edges4(ei, E, e0, is64, s, d);
            uint4 v[4];
#pragma unroll
            for (int i = 0; i < 4; i++)
                v[i] = y4[s[i] * 4 + c];
#pragma unroll
            for (int i = 0; i < 4; i++)
                red_add_bf16x8(aggb + d[i] * 64 + c * 16, v[i]);
            if (c == 0) {
#pragma unroll
                for (int i = 0; i < 4; i++)
                    atomicAdd(&g_deg[d[i]], 1.0f);
            }
        } else if (g == ngroups) {
            for (int e = ngroups * 4; e < E; e++) {
                int s = is64 ? (int)((const long long*)ei)[e] : ((const int*)ei)[e];
                int d = is64 ? (int)((const long long*)ei)[E + e] : ((const int*)ei)[E + e];
                uint4 v = y4[s * 4 + c];
                red_add_bf16x8(aggb + d * 64 + c * 16, v);
                if (c == 0) atomicAdd(&g_deg[d], 1.0f);
            }
        }
    }
}

// ================= kernel 3: node update + scalar layer-2 projections =========
__global__ void __launch_bounds__(256) k_node1(const float* __restrict__ b1,
                                               const float* __restrict__ W2l,
                                               const float* __restrict__ W2r,
                                               int n) {
    int t = blockIdx.x * blockDim.x + threadIdx.x;
    int node = t >> 3, c = t & 7;
    if (node >= n) return;
    float invd = 1.0f / fmaxf(g_deg[node], 1.0f);
    uint2 ab = ((const uint2*)g_agg1b)[node * 8 + c];
    float2 a0 = __bfloat1622float2(*(__nv_bfloat162*)&ab.x);
    float2 a1 = __bfloat1622float2(*(__nv_bfloat162*)&ab.y);
    float4 r = ((const float4*)g_r1)[node * 8 + c];
    float4 bb = ((const float4*)b1)[c];
    float4 h;
    h.x = fmaxf(fmaf(a0.x, invd, bb.x + r.x), 0.0f);
    h.y = fmaxf(fmaf(a0.y, invd, bb.y + r.y), 0.0f);
    h.z = fmaxf(fmaf(a1.x, invd, bb.z + r.z), 0.0f);
    h.w = fmaxf(fmaf(a1.y, invd, bb.w + r.w), 0.0f);
    float4 wl = ((const float4*)W2l)[c];
    float4 wr = ((const float4*)W2r)[c];
    float zl = h.x * wl.x + h.y * wl.y + h.z * wl.z + h.w * wl.w;
    float zr = h.x * wr.x + h.y * wr.y + h.z * wr.z + h.w * wr.w;
#pragma unroll
    for (int o = 1; o <= 4; o <<= 1) {
        zl += __shfl_xor_sync(0xFFFFFFFFu, zl, o);
        zr += __shfl_xor_sync(0xFFFFFFFFu, zr, o);
    }
    if (c == 0) {
        g_z2[node] = zl;
        g_r2[node] = zr;
    }
}

// ================= kernel 4: layer-2 scalar edge scatter ======================
__global__ void __launch_bounds__(256) k_edge2(const void* __restrict__ ei, int E) {
    int is64 = g_is64;
    int ngroups = E >> 2;
    int g = blockIdx.x * blockDim.x + threadIdx.x;
    if (g < ngroups) {
        int e0 = g * 4;
        int s[4], d[4];
        load_edges4(ei, E, e0, is64, s, d);
        float z[4];
#pragma unroll
        for (int i = 0; i < 4; i++) z[i] = g_z2[s[i]];
#pragma unroll
        for (int i = 0; i < 4; i++) atomicAdd(&g_agg2[d[i]], z[i]);
    } else if (g == ngroups) {
        for (int e = ngroups * 4; e < E; e++) {
            int s = is64 ? (int)((const long long*)ei)[e] : ((const int*)ei)[e];
            int d = is64 ? (int)((const long long*)ei)[E + e] : ((const int*)ei)[E + e];
            atomicAdd(&g_agg2[d], g_z2[s]);
        }
    }
}

// ================= kernel 5: final sigmoid ============
__global__ void k_out(float* __restrict__ out, const float* __restrict__ b2, int n) {
    int i = blockIdx.x * blockDim.x + threadIdx.x;
    if (i < n) {
        float inv = 1.0f / fmaxf(g_deg[i], 1.0f);
        float v = fmaf(g_agg2[i], inv, b2[0] + g_r2[i]);
        out[i] = 1.0f / (1.0f + expf(-v));
    }
}

// ---------------- launch ----------------
extern "C" void kernel_launch(void* const* d_in, const int* in_sizes, int n_in,
                              void* d_out, int out_size) {
    const float* x   = (const float*)d_in[0];
    const void*  ei  = d_in[1];
    const float* W1l = (const float*)d_in[2];
    const float* b1  = (const float*)d_in[3];
    const float* W1r = (const float*)d_in[4];
    const float* W2l = (const float*)d_in[5];
    const float* b2  = (const float*)d_in[6];
    const float* W2r = (const float*)d_in[7];
    float* out = (float*)d_out;

    int n = in_sizes[0] / DIN;
    int E = in_sizes[1] / 2;
    if (n > NMAX) n = NMAX;
    if (E > EMAX) E = EMAX;

    k_pre<<<740, 128>>>(x, W1l, (const unsigned int*)ei, n);
    int edge_blocks = (E + 4 + 255) / 256;
    k_fat<<<GB + edge_blocks, 256>>>(x, W1r, ei, n, E);
    k_node1<<<(n * 8 + 255) / 256, 256>>>(b1, W2l, W2r, n);
    int ng = (E >> 2) + 1;
    k_edge2<<<(ng + 255) / 256, 256>>>(ei, E);
    k_out<<<(n + 255) / 256, 256>>>(out, b2, n);
}